// round 16
// baseline (speedup 1.0000x reference)
#include <cuda_runtime.h>

#define BATCH     16384
#define QSEQ      1204
#define FDIM      7
#define NCAT      600
#define H1DIM     128
#define H2DIM     32
#define ODIM      2

#define NROWS     128        // rows per CTA
#define KT        40         // k per tile
#define NTILE     15         // 15*40 = 600
#define PROWS     16         // rows per producer warp (8 producer warps)
#define SEGS      (NTILE * PROWS)   // 240 segs per producer warp
#define QT        84         // dots per segment (80 + 4 lookahead)
#define F4T       147        // float4 per row-segment (588 floats)
#define XBUF_F    592        // padded per-row buffer (floats)
#define XRING     5          // 5-deep ring: 4 segs in flight
#define CPITCH    132        // cat tile pitch
#define WASTG     3          // wA ring stages

// smem layout (floats)
#define XSCR_OFF  0                         // 8 * 5 * 592 = 23680
#define DROW_OFF  23680                     // 8 * 96 = 768
#define CAT_OFF   24448                     // 2 * 40*132 = 10560
#define WA_OFF    35008                     // 3 * 40*128 = 15360
#define WB_OFF    50368                     // 4096
#define SM_F      54464
#define SM_BYTES  (SM_F * 4)                // 217856 B

// ---------------------------------------------------------------------------
__device__ __forceinline__ unsigned long long pack2(float lo, float hi) {
    unsigned long long r;
    asm("mov.b64 %0, {%1, %2};" : "=l"(r) : "f"(lo), "f"(hi));
    return r;
}
__device__ __forceinline__ void unpack2(unsigned long long v, float& lo, float& hi) {
    asm("mov.b64 {%0, %1}, %2;" : "=f"(lo), "=f"(hi) : "l"(v));
}
__device__ __forceinline__ unsigned long long ffma2(unsigned long long a,
                                                    unsigned long long b,
                                                    unsigned long long c) {
    unsigned long long d;
    asm("fma.rn.f32x2 %0, %1, %2, %3;" : "=l"(d) : "l"(a), "l"(b), "l"(c));
    return d;
}
__device__ __forceinline__ void cp_async16(void* smem_dst, const void* gsrc) {
    unsigned s = (unsigned)__cvta_generic_to_shared(smem_dst);
    asm volatile("cp.async.cg.shared.global [%0], [%1], 16;\n" :: "r"(s), "l"(gsrc));
}
__device__ __forceinline__ void cp_commit() {
    asm volatile("cp.async.commit_group;\n" ::: "memory");
}
__device__ __forceinline__ void cp_wait1() {
    asm volatile("cp.async.wait_group 1;\n" ::: "memory");
}
__device__ __forceinline__ void cp_wait4() {
    asm volatile("cp.async.wait_group 4;\n" ::: "memory");
}

// ===========================================================================
// Warp-specialized fused kernel. grid 128, 512 thr, 1 CTA/SM.
//   warps 0..7  : producers — x stream (5-deep ring) -> dots -> pool -> cat
//   warps 8..15 : consumers — wA prefetch (3-stage ring) + layer-A GEMM
// One __syncthreads per tile. Layers B, C by all warps at the end.
// ===========================================================================
__global__ __launch_bounds__(512, 1)
void fused_kernel(const float* __restrict__ x,
                  const float* __restrict__ w_step,
                  const float* __restrict__ b_step,
                  const float* __restrict__ wA,
                  const float* __restrict__ bA,
                  const float* __restrict__ wB,
                  const float* __restrict__ bB,
                  const float* __restrict__ wC,
                  const float* __restrict__ bC,
                  float* __restrict__ out)
{
    extern __shared__ float smem[];
    float* xscr = smem + XSCR_OFF;
    float* drow = smem + DROW_OFF;
    float* catb = smem + CAT_OFF;
    float* wab  = smem + WA_OFF;
    float* swB  = smem + WB_OFF;
    float* h1   = smem;                    // alias after mainloop (16384 fl)
    float* h2   = smem + H1DIM * NROWS;    // 4096 fl (ends before CAT_OFF)

    const int tid  = threadIdx.x;
    const int lane = tid & 31;
    const int w    = tid >> 5;
    const bool producer = (w < 8);
    const size_t b0 = (size_t)blockIdx.x * NROWS;

    // ---- producer state ----
    float wsv[FDIM];
#pragma unroll
    for (int f = 0; f < FDIM; ++f) wsv[f] = __ldg(&w_step[f]);
    const float bs = __ldg(b_step);

    const int wp = w;                               // producer warp id
    float* mybuf = xscr + (w & 7) * (XRING * XBUF_F);
    float* mydr  = drow + (w & 7) * 96;
    const size_t xrow0 = (b0 + (size_t)((w & 7) * PROWS)) * (size_t)(QSEQ * FDIM);

    auto issue_seg = [&](int s) {
        const int its = s >> 4;                     // tile
        const int is  = s & 15;                     // row within warp
        const float* src = x + xrow0 + (size_t)is * (QSEQ * FDIM)
                         + (size_t)its * 560;
        float* dst = mybuf + (s % XRING) * XBUF_F;
#pragma unroll
        for (int c0 = 0; c0 < 5; ++c0) {
            const int c = c0 * 32 + lane;
            if (c < F4T) cp_async16(dst + c * 4, src + c * 4);
        }
    };

    // ---- consumer state ----
    const int wc   = w - 8;                         // consumer warp id
    const int j0   = (w & 7) * 16;                  // 16 neurons per consumer
    const int r0c  = lane * 4;                      // 4 rows per lane
    const int ctid = (w & 7) * 32 + lane;           // consumer-local tid

    // acc[np][r]: neuron pair (j0+2np, j0+2np+1), row r0c+r
    unsigned long long acc[8][4];
#pragma unroll
    for (int n = 0; n < 8; ++n)
#pragma unroll
        for (int r = 0; r < 4; ++r) acc[n][r] = 0ULL;

    auto gemm_tile = [&](int tg) {
        const float* wt = wab  + (tg % WASTG) * (KT * H1DIM) + j0;
        const float* ct = catb + (tg & 1) * (KT * CPITCH) + r0c;
#pragma unroll 4
        for (int kk = 0; kk < KT; ++kk) {
            const ulonglong2 w0 = *(const ulonglong2*)(wt + kk * H1DIM);      // np 0,1
            const ulonglong2 w1 = *(const ulonglong2*)(wt + kk * H1DIM + 4);  // np 2,3
            const ulonglong2 w2 = *(const ulonglong2*)(wt + kk * H1DIM + 8);  // np 4,5
            const ulonglong2 w3 = *(const ulonglong2*)(wt + kk * H1DIM + 12); // np 6,7
            const float4 c = *(const float4*)(ct + kk * CPITCH);
            const unsigned long long c0 = pack2(c.x, c.x);
            const unsigned long long c1 = pack2(c.y, c.y);
            const unsigned long long c2 = pack2(c.z, c.z);
            const unsigned long long c3 = pack2(c.w, c.w);
            acc[0][0] = ffma2(w0.x, c0, acc[0][0]);
            acc[1][0] = ffma2(w0.y, c0, acc[1][0]);
            acc[2][0] = ffma2(w1.x, c0, acc[2][0]);
            acc[3][0] = ffma2(w1.y, c0, acc[3][0]);
            acc[4][0] = ffma2(w2.x, c0, acc[4][0]);
            acc[5][0] = ffma2(w2.y, c0, acc[5][0]);
            acc[6][0] = ffma2(w3.x, c0, acc[6][0]);
            acc[7][0] = ffma2(w3.y, c0, acc[7][0]);
            acc[0][1] = ffma2(w0.x, c1, acc[0][1]);
            acc[1][1] = ffma2(w0.y, c1, acc[1][1]);
            acc[2][1] = ffma2(w1.x, c1, acc[2][1]);
            acc[3][1] = ffma2(w1.y, c1, acc[3][1]);
            acc[4][1] = ffma2(w2.x, c1, acc[4][1]);
            acc[5][1] = ffma2(w2.y, c1, acc[5][1]);
            acc[6][1] = ffma2(w3.x, c1, acc[6][1]);
            acc[7][1] = ffma2(w3.y, c1, acc[7][1]);
            acc[0][2] = ffma2(w0.x, c2, acc[0][2]);
            acc[1][2] = ffma2(w0.y, c2, acc[1][2]);
            acc[2][2] = ffma2(w1.x, c2, acc[2][2]);
            acc[3][2] = ffma2(w1.y, c2, acc[3][2]);
            acc[4][2] = ffma2(w2.x, c2, acc[4][2]);
            acc[5][2] = ffma2(w2.y, c2, acc[5][2]);
            acc[6][2] = ffma2(w3.x, c2, acc[6][2]);
            acc[7][2] = ffma2(w3.y, c2, acc[7][2]);
            acc[0][3] = ffma2(w0.x, c3, acc[0][3]);
            acc[1][3] = ffma2(w0.y, c3, acc[1][3]);
            acc[2][3] = ffma2(w1.x, c3, acc[2][3]);
            acc[3][3] = ffma2(w1.y, c3, acc[3][3]);
            acc[4][3] = ffma2(w2.x, c3, acc[4][3]);
            acc[5][3] = ffma2(w2.y, c3, acc[5][3]);
            acc[6][3] = ffma2(w3.x, c3, acc[6][3]);
            acc[7][3] = ffma2(w3.y, c3, acc[7][3]);
        }
    };

    // ---- prologue ----
    if (producer) {
        issue_seg(0); cp_commit();
        issue_seg(1); cp_commit();
        issue_seg(2); cp_commit();
        issue_seg(3); cp_commit();
    } else {
        // group 0: wB + wA(0) (stage 0)
        for (int idx = ctid; idx < (H1DIM * H2DIM) / 4; idx += 256)
            cp_async16(swB + idx * 4, wB + idx * 4);
        for (int idx = ctid; idx < (KT * H1DIM) / 4; idx += 256)
            cp_async16(wab + idx * 4, wA + idx * 4);
        cp_commit();
    }

    // ---- main loop: one barrier per tile ----
    for (int t = 0; t < NTILE; ++t) {
        if (producer) {
            float* cb = catb + (t & 1) * (KT * CPITCH);
            for (int i = 0; i < PROWS; ++i) {
                const int s = t * PROWS + i;
                if (s + 4 < SEGS) issue_seg(s + 4);
                cp_commit();             // uniform group count
                cp_wait4();              // seg s landed
                __syncwarp();

                // dots: 84 queries, stride-7 conflict-free LDS
                const float* buf = mybuf + (s % XRING) * XBUF_F;
#pragma unroll
                for (int rd = 0; rd < 3; ++rd) {
                    const int q = rd * 32 + lane;
                    if (q < QT) {
                        const float* sq = buf + q * 7;
                        float a = bs;
#pragma unroll
                        for (int f = 0; f < 7; ++f) a = fmaf(sq[f], wsv[f], a);
                        mydr[q] = a;
                    }
                }
                __syncwarp();

                // pool: lanes 0..7 handle chunk ci
                if (lane < 8) {
                    const int ci = lane;
                    const float* dr = mydr + ci * 10;
                    float v[14];
#pragma unroll
                    for (int j = 0; j < 14; ++j) v[j] = dr[j];

                    float common = v[4];
#pragma unroll
                    for (int j = 5; j < 10; ++j) common = fmaxf(common, v[j]);
                    const float P1 = v[10];
                    const float P2 = fmaxf(P1, v[11]);
                    const float P3 = fmaxf(P2, v[12]);
                    const float P4 = fmaxf(P3, v[13]);
                    const float T3 = v[3];
                    const float T2 = fmaxf(v[2], T3);
                    const float T1 = fmaxf(v[1], T2);
                    const float T0 = fmaxf(v[0], T1);

                    const int r  = (w & 7) * PROWS + i;
                    const int k0 = 5 * ci;
                    cb[(k0 + 0) * CPITCH + r] = fmaxf(common, T0);
                    cb[(k0 + 1) * CPITCH + r] = fmaxf(fmaxf(common, T1), P1);
                    cb[(k0 + 2) * CPITCH + r] = fmaxf(fmaxf(common, T2), P2);
                    cb[(k0 + 3) * CPITCH + r] = fmaxf(fmaxf(common, T3), P3);
                    cb[(k0 + 4) * CPITCH + r] = fmaxf(common, P4);
                }
                __syncwarp();            // drow WAR before next row
            }
        } else {
            // prefetch wA(t+1) into stage (t+1)%3 (stage being neither
            // read (t-1) nor owed to this tile (t))
            if (t + 1 < NTILE) {
                const float* wsrc = wA + (size_t)(t + 1) * (KT * H1DIM);
                float* wdst = wab + ((t + 1) % WASTG) * (KT * H1DIM);
                for (int idx = ctid; idx < (KT * H1DIM) / 4; idx += 256)
                    cp_async16(wdst + idx * 4, wsrc + idx * 4);
            }
            cp_commit();
            cp_wait1();                  // wA(t) (and older) landed
            if (t >= 1) gemm_tile(t - 1);
        }
        __syncthreads();                 // publish cat(t); close ring WAR
    }

    // ---- tail: consumers GEMM the last tile, write h1 ----
    if (!producer) {
        gemm_tile(NTILE - 1);

        float4 ba0 = *(const float4*)&bA[j0];
        float4 ba1 = *(const float4*)&bA[j0 + 4];
        float4 ba2 = *(const float4*)&bA[j0 + 8];
        float4 ba3 = *(const float4*)&bA[j0 + 12];
        const float bb[16] = {ba0.x, ba0.y, ba0.z, ba0.w,
                              ba1.x, ba1.y, ba1.z, ba1.w,
                              ba2.x, ba2.y, ba2.z, ba2.w,
                              ba3.x, ba3.y, ba3.z, ba3.w};
        float lo, hi;
#pragma unroll
        for (int np = 0; np < 8; ++np) {
#pragma unroll
            for (int r = 0; r < 4; ++r) {
                unpack2(acc[np][r], lo, hi);
                h1[(j0 + 2*np + 0) * NROWS + r0c + r] = fmaxf(lo + bb[2*np + 0], 0.0f);
                h1[(j0 + 2*np + 1) * NROWS + r0c + r] = fmaxf(hi + bb[2*np + 1], 0.0f);
            }
        }
    }
    __syncthreads();

    // ---- Layer B: all warps. h2[r][m] = relu(sum_j h1[j][r]*wB[j][m]+bB[m]) ----
    {
        const int m  = tid & 31;
        const int rb = (tid >> 5) * 8;           // 16 warps x 8 rows = 128
        float s[8];
#pragma unroll
        for (int r = 0; r < 8; ++r) s[r] = 0.0f;
#pragma unroll 8
        for (int j = 0; j < H1DIM; ++j) {
            const float wb = swB[j * H2DIM + m];
            const float4 h0 = *(const float4*)&h1[j * NROWS + rb];
            const float4 h1v = *(const float4*)&h1[j * NROWS + rb + 4];
            s[0] = fmaf(h0.x, wb, s[0]);
            s[1] = fmaf(h0.y, wb, s[1]);
            s[2] = fmaf(h0.z, wb, s[2]);
            s[3] = fmaf(h0.w, wb, s[3]);
            s[4] = fmaf(h1v.x, wb, s[4]);
            s[5] = fmaf(h1v.y, wb, s[5]);
            s[6] = fmaf(h1v.z, wb, s[6]);
            s[7] = fmaf(h1v.w, wb, s[7]);
        }
        const float bm = __ldg(&bB[m]);
#pragma unroll
        for (int r = 0; r < 8; ++r)
            h2[(rb + r) * H2DIM + m] = fmaxf(s[r] + bm, 0.0f);
    }
    __syncthreads();

    // ---- Layer C ----
    if (tid < NROWS * ODIM) {
        const int r = tid >> 1;
        const int c = tid & 1;
        float s = __ldg(&bC[c]);
#pragma unroll
        for (int m = 0; m < H2DIM; ++m)
            s = fmaf(h2[r * H2DIM + m], __ldg(&wC[m * ODIM + c]), s);
        out[(b0 + (size_t)r) * ODIM + c] = s;
    }
}

extern "C" void kernel_launch(void* const* d_in, const int* in_sizes, int n_in,
                              void* d_out, int out_size)
{
    const float* x      = (const float*)d_in[0];
    const float* w_step = (const float*)d_in[1];
    const float* b_step = (const float*)d_in[2];
    const float* wA     = (const float*)d_in[3];
    const float* bA     = (const float*)d_in[4];
    const float* wB     = (const float*)d_in[5];
    const float* bB     = (const float*)d_in[6];
    const float* wC     = (const float*)d_in[7];
    const float* bC     = (const float*)d_in[8];
    float* out          = (float*)d_out;

    cudaFuncSetAttribute(fused_kernel, cudaFuncAttributeMaxDynamicSharedMemorySize, SM_BYTES);

    fused_kernel<<<BATCH / NROWS, 512, SM_BYTES>>>(
        x, w_step, b_step, wA, bA, wB, bB, wC, bC, out);
}

// round 17
// speedup vs baseline: 1.1649x; 1.1649x over previous
#include <cuda_runtime.h>

#define BATCH     16384
#define QSEQ      1204
#define FDIM      7
#define NCAT      600
#define H1DIM     128
#define H2DIM     32
#define ODIM      2

#define NROWS     128        // rows per CTA
#define KT        40         // k per tile = 8 pool-chunks
#define NTILE     15         // 15*40 = 600
#define SEGS      (NTILE * 8)  // 120 row-segments per warp
#define QT        84         // dots per segment (80 + 4 lookahead)
#define F4T       147        // float4 per row-segment (588 floats)
#define XBUF_F    592        // padded per-warp row buffer (floats)
#define CPITCH    132        // cat tile pitch
#define KCHUNK    5          // GEMM k-steps interleaved per row iteration

// smem layout (floats)
#define XSCR_OFF  0                         // 16 warps * 3 * 592 = 28416
#define DROW_OFF  28416                     // 16 * 96 = 1536
#define CAT_OFF   29952                     // 2 * 40*132 = 10560
#define WA_OFF    40512                     // 2 * 40*128 = 10240
#define WB_OFF    50752                     // 4096
#define SM_F      54848
#define SM_BYTES  (SM_F * 4)                // 219392 B

// ---------------------------------------------------------------------------
__device__ __forceinline__ unsigned long long pack2(float lo, float hi) {
    unsigned long long r;
    asm("mov.b64 %0, {%1, %2};" : "=l"(r) : "f"(lo), "f"(hi));
    return r;
}
__device__ __forceinline__ void unpack2(unsigned long long v, float& lo, float& hi) {
    asm("mov.b64 {%0, %1}, %2;" : "=f"(lo), "=f"(hi) : "l"(v));
}
__device__ __forceinline__ unsigned long long ffma2(unsigned long long a,
                                                    unsigned long long b,
                                                    unsigned long long c) {
    unsigned long long d;
    asm("fma.rn.f32x2 %0, %1, %2, %3;" : "=l"(d) : "l"(a), "l"(b), "l"(c));
    return d;
}
__device__ __forceinline__ void cp_async16(void* smem_dst, const void* gsrc) {
    unsigned s = (unsigned)__cvta_generic_to_shared(smem_dst);
    asm volatile("cp.async.cg.shared.global [%0], [%1], 16;\n" :: "r"(s), "l"(gsrc));
}
__device__ __forceinline__ void cp_commit() {
    asm volatile("cp.async.commit_group;\n" ::: "memory");
}
__device__ __forceinline__ void cp_wait2() {
    asm volatile("cp.async.wait_group 2;\n" ::: "memory");
}

// ===========================================================================
// Fused kernel (R15 structure), GEMM re-paired:
//   FFMA2 lanes = NEURON pairs (wA ulonglong2, zero movs);
//   rows splatted (4 movs per k instead of 8).
// row iteration i of tile it: issue seg s+2 -> wait seg s -> dots -> pool
//                             -> 5 GEMM k-steps of tile it-1.
// ONE CTA barrier per tile; tail GEMM after loop. grid 128, 512 thr, 1 CTA/SM.
// ===========================================================================
__global__ __launch_bounds__(512, 1)
void fused_kernel(const float* __restrict__ x,
                  const float* __restrict__ w_step,
                  const float* __restrict__ b_step,
                  const float* __restrict__ wA,
                  const float* __restrict__ bA,
                  const float* __restrict__ wB,
                  const float* __restrict__ bB,
                  const float* __restrict__ wC,
                  const float* __restrict__ bC,
                  float* __restrict__ out)
{
    extern __shared__ float smem[];
    float* xscr = smem + XSCR_OFF;    // per-warp 3-deep x ring
    float* drow = smem + DROW_OFF;    // per-warp dot row (96 pitch)
    float* catb = smem + CAT_OFF;     // cat ring (2 stages, pitch 132)
    float* wab  = smem + WA_OFF;      // wA ring (2 stages, pitch 128)
    float* swB  = smem + WB_OFF;      // persistent wB
    float* h1   = smem;               // alias after mainloop
    float* h2   = smem + H1DIM * NROWS;

    const int tid  = threadIdx.x;
    const int lane = tid & 31;
    const int w    = tid >> 5;                 // 0..15
    const size_t b0 = (size_t)blockIdx.x * NROWS;

    float wsv[FDIM];
#pragma unroll
    for (int f = 0; f < FDIM; ++f) wsv[f] = __ldg(&w_step[f]);
    const float bs = __ldg(b_step);

    float* mybuf = xscr + w * (3 * XBUF_F);
    float* mydr  = drow + w * 96;
    const size_t xrow0 = (b0 + (size_t)(w * 8)) * (size_t)(QSEQ * FDIM);

    auto issue_seg = [&](int s) {
        const int its = s >> 3;
        const int is  = s & 7;
        const float* src = x + xrow0 + (size_t)its * 560
                         + (size_t)is * (QSEQ * FDIM) + lane * 4;
        float* dst = mybuf + (s % 3) * XBUF_F + lane * 4;
#pragma unroll
        for (int c0 = 0; c0 < 5; ++c0) {
            if (c0 * 32 + lane < F4T)
                cp_async16(dst + c0 * 128, src + c0 * 128);
        }
    };

    // ---- prologue: group = {wB, wA(0)}; then seg 0, seg 1 ----
    for (int idx = tid; idx < (H1DIM * H2DIM) / 4; idx += 512)
        cp_async16(swB + idx * 4, wB + idx * 4);
    for (int idx = tid; idx < (KT * H1DIM) / 4; idx += 512)
        cp_async16(wab + idx * 4, wA + idx * 4);
    cp_commit();
    issue_seg(0); cp_commit();
    issue_seg(1); cp_commit();

    // GEMM accumulators: acc[np][r] = neuron pair (j0+2np, j0+2np+1), row r0c+r
    unsigned long long acc[4][4];
#pragma unroll
    for (int n = 0; n < 4; ++n)
#pragma unroll
        for (int r = 0; r < 4; ++r) acc[n][r] = 0ULL;
    const int j0  = w * 8;
    const int r0c = lane * 4;

    // one GEMM k-chunk of tile tg (ring stage tg&1), kk in [k0, k0+KCHUNK)
    auto gemm_chunk = [&](int tg, int k0) {
        const float* wt = wab  + (tg & 1) * (KT * H1DIM) + j0;
        const float* ct = catb + (tg & 1) * (KT * CPITCH) + r0c;
#pragma unroll
        for (int kq = 0; kq < KCHUNK; ++kq) {
            const int kk = k0 + kq;
            const ulonglong2 wp0 = *(const ulonglong2*)(wt + kk * H1DIM);     // pairs (j0,j0+1),(j0+2,j0+3)
            const ulonglong2 wp1 = *(const ulonglong2*)(wt + kk * H1DIM + 4); // pairs (j0+4,j0+5),(j0+6,j0+7)
            const float4 c = *(const float4*)(ct + kk * CPITCH);              // rows r0c..r0c+3
            const unsigned long long c0 = pack2(c.x, c.x);
            const unsigned long long c1 = pack2(c.y, c.y);
            const unsigned long long c2 = pack2(c.z, c.z);
            const unsigned long long c3 = pack2(c.w, c.w);
            acc[0][0] = ffma2(wp0.x, c0, acc[0][0]);
            acc[1][0] = ffma2(wp0.y, c0, acc[1][0]);
            acc[2][0] = ffma2(wp1.x, c0, acc[2][0]);
            acc[3][0] = ffma2(wp1.y, c0, acc[3][0]);
            acc[0][1] = ffma2(wp0.x, c1, acc[0][1]);
            acc[1][1] = ffma2(wp0.y, c1, acc[1][1]);
            acc[2][1] = ffma2(wp1.x, c1, acc[2][1]);
            acc[3][1] = ffma2(wp1.y, c1, acc[3][1]);
            acc[0][2] = ffma2(wp0.x, c2, acc[0][2]);
            acc[1][2] = ffma2(wp0.y, c2, acc[1][2]);
            acc[2][2] = ffma2(wp1.x, c2, acc[2][2]);
            acc[3][2] = ffma2(wp1.y, c2, acc[3][2]);
            acc[0][3] = ffma2(wp0.x, c3, acc[0][3]);
            acc[1][3] = ffma2(wp0.y, c3, acc[1][3]);
            acc[2][3] = ffma2(wp1.x, c3, acc[2][3]);
            acc[3][3] = ffma2(wp1.y, c3, acc[3][3]);
        }
    };

    for (int it = 0; it < NTILE; ++it) {
        float* cb = catb + (it & 1) * (KT * CPITCH);

        for (int i = 0; i < 8; ++i) {
            const int s = it * 8 + i;
            if (s + 2 < SEGS) {
                issue_seg(s + 2);
                if (i == 0 && it >= 1) {
                    const float* wsrc = wA + (size_t)it * (KT * H1DIM);
                    float* wdst = wab + (it & 1) * (KT * H1DIM);
                    for (int idx = tid; idx < (KT * H1DIM) / 4; idx += 512)
                        cp_async16(wdst + idx * 4, wsrc + idx * 4);
                }
            }
            cp_commit();             // uniform: one group per seg slot
            cp_wait2();              // seg s landed
            __syncwarp();

            // dots for row i of tile it (84 queries), stride-7 LDS
            const float* buf = mybuf + (s % 3) * XBUF_F;
#pragma unroll
            for (int rd = 0; rd < 3; ++rd) {
                const int q = rd * 32 + lane;
                if (q < QT) {
                    const float* sq = buf + q * 7;
                    float a = bs;
#pragma unroll
                    for (int f = 0; f < 7; ++f) a = fmaf(sq[f], wsv[f], a);
                    mydr[q] = a;
                }
            }
            __syncwarp();

            // per-row pooling: lanes 0..7 handle chunk ci
            if (lane < 8) {
                const int ci = lane;
                const float* dr = mydr + ci * 10;
                float v[14];
#pragma unroll
                for (int j = 0; j < 14; ++j) v[j] = dr[j];

                float common = v[4];
#pragma unroll
                for (int j = 5; j < 10; ++j) common = fmaxf(common, v[j]);
                const float P1 = v[10];
                const float P2 = fmaxf(P1, v[11]);
                const float P3 = fmaxf(P2, v[12]);
                const float P4 = fmaxf(P3, v[13]);
                const float T3 = v[3];
                const float T2 = fmaxf(v[2], T3);
                const float T1 = fmaxf(v[1], T2);
                const float T0 = fmaxf(v[0], T1);

                const int r  = w * 8 + i;
                const int k0 = 5 * ci;
                cb[(k0 + 0) * CPITCH + r] = fmaxf(common, T0);
                cb[(k0 + 1) * CPITCH + r] = fmaxf(fmaxf(common, T1), P1);
                cb[(k0 + 2) * CPITCH + r] = fmaxf(fmaxf(common, T2), P2);
                cb[(k0 + 3) * CPITCH + r] = fmaxf(fmaxf(common, T3), P3);
                cb[(k0 + 4) * CPITCH + r] = fmaxf(common, P4);
            }
            __syncwarp();            // drow WAR before next row's dots

            // ---- interleaved GEMM: 5 k-steps of tile it-1 ----
            if (it >= 1) gemm_chunk(it - 1, i * KCHUNK);
        }
        __syncthreads();             // publish cat(it)+wA(it); ring WAR closed
    }

    // ---- tail GEMM: tile NTILE-1, all 40 k-steps ----
#pragma unroll
    for (int i = 0; i < 8; ++i) gemm_chunk(NTILE - 1, i * KCHUNK);

    // ---- epilogue: h1 = relu(acc + bias), layout h1[j*128 + r] ----
    const float4 ba0 = *(const float4*)&bA[j0];
    const float4 ba1 = *(const float4*)&bA[j0 + 4];
    {
        const float bb[8] = {ba0.x, ba0.y, ba0.z, ba0.w, ba1.x, ba1.y, ba1.z, ba1.w};
        float lo, hi;
#pragma unroll
        for (int np = 0; np < 4; ++np) {
#pragma unroll
            for (int r = 0; r < 4; ++r) {
                unpack2(acc[np][r], lo, hi);
                h1[(j0 + 2*np + 0) * NROWS + r0c + r] = fmaxf(lo + bb[2*np + 0], 0.0f);
                h1[(j0 + 2*np + 1) * NROWS + r0c + r] = fmaxf(hi + bb[2*np + 1], 0.0f);
            }
        }
    }
    __syncthreads();

    // ---- Layer B ----
    {
        const int m  = tid & 31;
        const int rb = (tid >> 5) * 8;           // 16 warps x 8 rows = 128
        float s[8];
#pragma unroll
        for (int r = 0; r < 8; ++r) s[r] = 0.0f;
#pragma unroll 8
        for (int j = 0; j < H1DIM; ++j) {
            const float wb = swB[j * H2DIM + m];
            const float4 h0 = *(const float4*)&h1[j * NROWS + rb];
            const float4 h1v = *(const float4*)&h1[j * NROWS + rb + 4];
            s[0] = fmaf(h0.x, wb, s[0]);
            s[1] = fmaf(h0.y, wb, s[1]);
            s[2] = fmaf(h0.z, wb, s[2]);
            s[3] = fmaf(h0.w, wb, s[3]);
            s[4] = fmaf(h1v.x, wb, s[4]);
            s[5] = fmaf(h1v.y, wb, s[5]);
            s[6] = fmaf(h1v.z, wb, s[6]);
            s[7] = fmaf(h1v.w, wb, s[7]);
        }
        const float bm = __ldg(&bB[m]);
#pragma unroll
        for (int r = 0; r < 8; ++r)
            h2[(rb + r) * H2DIM + m] = fmaxf(s[r] + bm, 0.0f);
    }
    __syncthreads();

    // ---- Layer C ----
    if (tid < NROWS * ODIM) {
        const int r = tid >> 1;
        const int c = tid & 1;
        float s = __ldg(&bC[c]);
#pragma unroll
        for (int m = 0; m < H2DIM; ++m)
            s = fmaf(h2[r * H2DIM + m], __ldg(&wC[m * ODIM + c]), s);
        out[(b0 + (size_t)r) * ODIM + c] = s;
    }
}

extern "C" void kernel_launch(void* const* d_in, const int* in_sizes, int n_in,
                              void* d_out, int out_size)
{
    const float* x      = (const float*)d_in[0];
    const float* w_step = (const float*)d_in[1];
    const float* b_step = (const float*)d_in[2];
    const float* wA     = (const float*)d_in[3];
    const float* bA     = (const float*)d_in[4];
    const float* wB     = (const float*)d_in[5];
    const float* bB     = (const float*)d_in[6];
    const float* wC     = (const float*)d_in[7];
    const float* bC     = (const float*)d_in[8];
    float* out          = (float*)d_out;

    cudaFuncSetAttribute(fused_kernel, cudaFuncAttributeMaxDynamicSharedMemorySize, SM_BYTES);

    fused_kernel<<<BATCH / NROWS, 512, SM_BYTES>>>(
        x, w_step, b_step, wA, bA, wB, bB, wC, bC, out);
}